// round 1
// baseline (speedup 1.0000x reference)
#include <cuda_runtime.h>
#include <cuda_bf16.h>
#include <math.h>
#include <stdint.h>

// Problem constants
#define TOKS   131072      // 32 * 4096 tokens
#define CD     256         // model dim
#define HIDD   1024        // mlp hidden
#define NHEAD  8
#define HD     32          // head dim
#define NWIN   64          // tokens per window (8x8)

typedef __nv_bfloat16 bf16;

// ---------------- scratch (static device globals; no allocation) -------------
__device__ bf16  g_xn[(size_t)TOKS * CD];          // LN1 output (bf16)
__device__ bf16  g_qkv[(size_t)TOKS * 3 * CD];     // qkv (bf16)
__device__ bf16  g_attn[(size_t)TOKS * CD];        // attention output (bf16)
__device__ float g_x1[(size_t)TOKS * CD];          // residual 1 (fp32)
__device__ bf16  g_x1n[(size_t)TOKS * CD];         // LN2 output (bf16)
__device__ bf16  g_h[(size_t)TOKS * HIDD];         // gelu(fc1) (bf16)
__device__ bf16  g_wqkv[768 * 256];
__device__ bf16  g_wproj[256 * 256];
__device__ bf16  g_wfc1[1024 * 256];
__device__ bf16  g_wfc2[256 * 1024];
__device__ float g_bias[NHEAD * NWIN * NWIN];      // [h][n][m]

// ---------------- helpers ----------------------------------------------------
__device__ __forceinline__ void ldsm4(uint32_t* r, uint32_t addr) {
    asm volatile("ldmatrix.sync.aligned.m8n8.x4.shared.b16 {%0,%1,%2,%3}, [%4];\n"
                 : "=r"(r[0]), "=r"(r[1]), "=r"(r[2]), "=r"(r[3]) : "r"(addr));
}

__device__ __forceinline__ void mma16816(float* c, const uint32_t* a,
                                         uint32_t b0, uint32_t b1) {
    asm volatile("mma.sync.aligned.m16n8k16.row.col.f32.bf16.bf16.f32 "
                 "{%0,%1,%2,%3}, {%4,%5,%6,%7}, {%8,%9}, {%0,%1,%2,%3};\n"
                 : "+f"(c[0]), "+f"(c[1]), "+f"(c[2]), "+f"(c[3])
                 : "r"(a[0]), "r"(a[1]), "r"(a[2]), "r"(a[3]), "r"(b0), "r"(b1));
}

// token index for (window, pos-in-window). H = W = 64, WS = 8.
__device__ __forceinline__ int token_of(int win, int n) {
    int b  = win >> 6;
    int wr = (win >> 3) & 7;
    int wc = win & 7;
    int r  = n >> 3;
    int c  = n & 7;
    return (b << 12) | (((wr << 3) + r) << 6) | ((wc << 3) + c);
}

// ---------------- prep: weight bf16 conversion + rel-pos bias ----------------
__global__ void prep_kernel(const float* __restrict__ wqkv, const float* __restrict__ wproj,
                            const float* __restrict__ wfc1, const float* __restrict__ wfc2,
                            const float* __restrict__ table) {
    int i = blockIdx.x * 256 + threadIdx.x;   // grid covers 262144
    if (i < 196608) g_wqkv[i] = __float2bfloat16(wqkv[i]);
    if (i < 65536)  g_wproj[i] = __float2bfloat16(wproj[i]);
    if (i < 262144) g_wfc1[i] = __float2bfloat16(wfc1[i]);
    if (i < 262144) g_wfc2[i] = __float2bfloat16(wfc2[i]);
    if (i < 32768) {
        int h = i >> 12;
        int n = (i >> 6) & 63;
        int m = i & 63;
        int rid = ((n >> 3) - (m >> 3) + 7) * 15 + ((n & 7) - (m & 7) + 7);
        g_bias[i] = table[rid * NHEAD + h];
    }
}

// ---------------- LayerNorm: one warp per token row --------------------------
// SRC==0: in = x (param), out = g_xn.  SRC==1: in = g_x1, out = g_x1n.
template <int SRC>
__global__ void ln_kernel(const float* __restrict__ x, const float* __restrict__ g,
                          const float* __restrict__ b) {
    int row  = blockIdx.x * 8 + threadIdx.y;
    int lane = threadIdx.x;
    const float* xr = (SRC == 0 ? x : g_x1) + (size_t)row * CD;
    float v[8];
    float s = 0.f;
#pragma unroll
    for (int i = 0; i < 8; i++) { v[i] = xr[lane + 32 * i]; s += v[i]; }
#pragma unroll
    for (int o = 16; o; o >>= 1) s += __shfl_xor_sync(0xffffffffu, s, o);
    float mu = s * (1.f / 256.f);
    float q = 0.f;
#pragma unroll
    for (int i = 0; i < 8; i++) { float d = v[i] - mu; q += d * d; }
#pragma unroll
    for (int o = 16; o; o >>= 1) q += __shfl_xor_sync(0xffffffffu, q, o);
    float inv = rsqrtf(q * (1.f / 256.f) + 1e-5f);
    bf16* orow = (SRC == 0 ? g_xn : g_x1n) + (size_t)row * CD;
#pragma unroll
    for (int i = 0; i < 8; i++) {
        int c = lane + 32 * i;
        orow[c] = __float2bfloat16((v[i] - mu) * inv * g[c] + b[c]);
    }
}

// ---------------- GEMM: C[M,N] = A[M,K] @ W[N,K]^T (+epilogue) ---------------
// BM=128 BN=128 BK=64, 256 threads, 8 warps (4 m x 2 n), warp tile 32x64.
// MODE 0: qkv  (A=g_xn,  W=g_wqkv, K=256,  N=768,  out bf16 g_qkv, +bias)
// MODE 1: proj (A=g_attn,W=g_wproj,K=256,  N=256,  out f32 g_x1, +bias +x)
// MODE 2: fc1  (A=g_x1n, W=g_wfc1, K=256,  N=1024, out bf16 g_h, +bias, gelu)
// MODE 3: fc2  (A=g_h,   W=g_wfc2, K=1024, N=256,  out f32 d_out, +bias +g_x1)
template <int MODE>
__global__ void __launch_bounds__(256) gemm_kernel(const float* __restrict__ bias,
                                                   const float* __restrict__ res,
                                                   float* __restrict__ outf) {
    constexpr int KD = (MODE == 3) ? 1024 : 256;
    constexpr int ND = (MODE == 0) ? 768 : (MODE == 2) ? 1024 : 256;
    const bf16* A = (MODE == 0) ? g_xn : (MODE == 1) ? g_attn : (MODE == 2) ? g_x1n : g_h;
    const bf16* W = (MODE == 0) ? g_wqkv : (MODE == 1) ? g_wproj : (MODE == 2) ? g_wfc1 : g_wfc2;

    __shared__ __align__(16) bf16 As[128][72];
    __shared__ __align__(16) bf16 Bs[128][72];

    int tid  = threadIdx.x;
    int lane = tid & 31;
    int wid  = tid >> 5;
    int wm   = wid & 3;      // warp row  (0..3) -> 32 rows each
    int wn   = wid >> 2;     // warp col  (0..1) -> 64 cols each
    int m0   = blockIdx.y * 128;
    int n0   = blockIdx.x * 128;

    float acc[2][8][4];
#pragma unroll
    for (int i = 0; i < 2; i++)
#pragma unroll
        for (int j = 0; j < 8; j++)
#pragma unroll
            for (int k = 0; k < 4; k++) acc[i][j][k] = 0.f;

    int lr = tid >> 3;             // 0..31
    int lc = (tid & 7) << 3;       // 0,8,...,56

    for (int kt = 0; kt < KD; kt += 64) {
        const bf16* Ag = A + (size_t)(m0 + lr) * KD + kt + lc;
        const bf16* Wg = W + (size_t)(n0 + lr) * KD + kt + lc;
#pragma unroll
        for (int p = 0; p < 4; p++) {
            *(uint4*)&As[lr + 32 * p][lc] = *(const uint4*)(Ag + (size_t)32 * p * KD);
            *(uint4*)&Bs[lr + 32 * p][lc] = *(const uint4*)(Wg + (size_t)32 * p * KD);
        }
        __syncthreads();
#pragma unroll
        for (int ks = 0; ks < 4; ks++) {
            uint32_t a[2][4], b[4][4];
#pragma unroll
            for (int mf = 0; mf < 2; mf++) {
                uint32_t ad = (uint32_t)__cvta_generic_to_shared(
                    &As[wm * 32 + mf * 16 + (lane & 15)][ks * 16 + ((lane >> 4) << 3)]);
                ldsm4(a[mf], ad);
            }
#pragma unroll
            for (int np = 0; np < 4; np++) {
                uint32_t ad = (uint32_t)__cvta_generic_to_shared(
                    &Bs[wn * 64 + np * 16 + ((lane >> 4) << 3) + (lane & 7)]
                       [ks * 16 + (((lane >> 3) & 1) << 3)]);
                ldsm4(b[np], ad);
            }
#pragma unroll
            for (int mf = 0; mf < 2; mf++)
#pragma unroll
                for (int nf = 0; nf < 8; nf++)
                    mma16816(acc[mf][nf], a[mf], b[nf >> 1][(nf & 1) * 2],
                             b[nf >> 1][(nf & 1) * 2 + 1]);
        }
        __syncthreads();
    }

    // epilogue
    int er = lane >> 2;            // 0..7
    int ec = (lane & 3) << 1;      // 0,2,4,6
#pragma unroll
    for (int mf = 0; mf < 2; mf++) {
#pragma unroll
        for (int nf = 0; nf < 8; nf++) {
            int col = n0 + wn * 64 + nf * 8 + ec;
            float bx = bias[col], by = bias[col + 1];
#pragma unroll
            for (int half = 0; half < 2; half++) {
                int row = m0 + wm * 32 + mf * 16 + er + half * 8;
                float v0 = acc[mf][nf][half * 2] + bx;
                float v1 = acc[mf][nf][half * 2 + 1] + by;
                size_t o = (size_t)row * ND + col;
                if (MODE == 0) {
                    *(__nv_bfloat162*)(g_qkv + o) = __floats2bfloat162_rn(v0, v1);
                } else if (MODE == 1) {
                    float2 r2 = *(const float2*)&res[o];
                    g_x1[o]     = v0 + r2.x;
                    g_x1[o + 1] = v1 + r2.y;
                } else if (MODE == 2) {
                    float gx = 0.5f * v0 * (1.0f + erff(v0 * 0.70710678118654752f));
                    float gy = 0.5f * v1 * (1.0f + erff(v1 * 0.70710678118654752f));
                    *(__nv_bfloat162*)(g_h + o) = __floats2bfloat162_rn(gx, gy);
                } else {
                    float2 r2 = *(const float2*)&g_x1[o];
                    outf[o]     = v0 + r2.x;
                    outf[o + 1] = v1 + r2.y;
                }
            }
        }
    }
}

// ---------------- Attention: one block per (window, head) --------------------
__global__ void __launch_bounds__(128) attn_kernel() {
    __shared__ float Qs[64][33];
    __shared__ float Ks[64][33];
    __shared__ float Vs[64][33];
    __shared__ float Ss[64][65];

    int win = blockIdx.x;
    int h   = blockIdx.y;
    int tid = threadIdx.x;

    // preload bias into score tile
    for (int e = tid; e < 4096; e += 128)
        Ss[e >> 6][e & 63] = g_bias[(h << 12) + e];

    const float scale = 0.17677669529663687f;   // 32^-0.5
#pragma unroll
    for (int i = 0; i < 16; i++) {
        int e = tid + i * 128;
        int n = e >> 5, d = e & 31;
        size_t base = (size_t)token_of(win, n) * 768 + h * 32 + d;
        Qs[n][d] = __bfloat162float(g_qkv[base]) * scale;
        Ks[n][d] = __bfloat162float(g_qkv[base + 256]);
        Vs[n][d] = __bfloat162float(g_qkv[base + 512]);
    }
    __syncthreads();

    // S = Q K^T + bias      (thread tile: 4 rows x 8 cols)
    {
        int tr = tid >> 3, tc = tid & 7;
        float acc[4][8];
#pragma unroll
        for (int i = 0; i < 4; i++)
#pragma unroll
            for (int j = 0; j < 8; j++) acc[i][j] = 0.f;
#pragma unroll 8
        for (int d = 0; d < 32; d++) {
            float q[4], k[8];
#pragma unroll
            for (int i = 0; i < 4; i++) q[i] = Qs[tr * 4 + i][d];
#pragma unroll
            for (int j = 0; j < 8; j++) k[j] = Ks[tc * 8 + j][d];
#pragma unroll
            for (int i = 0; i < 4; i++)
#pragma unroll
                for (int j = 0; j < 8; j++) acc[i][j] = fmaf(q[i], k[j], acc[i][j]);
        }
#pragma unroll
        for (int i = 0; i < 4; i++)
#pragma unroll
            for (int j = 0; j < 8; j++) Ss[tr * 4 + i][tc * 8 + j] += acc[i][j];
    }
    __syncthreads();

    // softmax over rows
    if (tid < 64) {
        float mx = -1e30f;
#pragma unroll 8
        for (int m = 0; m < 64; m++) mx = fmaxf(mx, Ss[tid][m]);
        float s = 0.f;
#pragma unroll 8
        for (int m = 0; m < 64; m++) {
            float e = expf(Ss[tid][m] - mx);
            Ss[tid][m] = e;
            s += e;
        }
        float inv = 1.f / s;
#pragma unroll 8
        for (int m = 0; m < 64; m++) Ss[tid][m] *= inv;
    }
    __syncthreads();

    // O = P V               (thread tile: 4 rows x 4 dims)
    {
        int tr = tid >> 3, d0 = (tid & 7) << 2;
        float o[4][4];
#pragma unroll
        for (int i = 0; i < 4; i++)
#pragma unroll
            for (int j = 0; j < 4; j++) o[i][j] = 0.f;
#pragma unroll 8
        for (int m = 0; m < 64; m++) {
            float p[4], vv[4];
#pragma unroll
            for (int i = 0; i < 4; i++) p[i] = Ss[tr * 4 + i][m];
#pragma unroll
            for (int j = 0; j < 4; j++) vv[j] = Vs[m][d0 + j];
#pragma unroll
            for (int i = 0; i < 4; i++)
#pragma unroll
                for (int j = 0; j < 4; j++) o[i][j] = fmaf(p[i], vv[j], o[i][j]);
        }
#pragma unroll
        for (int i = 0; i < 4; i++) {
            int n = tr * 4 + i;
            size_t base = (size_t)token_of(win, n) * 256 + h * 32 + d0;
            __nv_bfloat162* p2 = (__nv_bfloat162*)(g_attn + base);
            p2[0] = __floats2bfloat162_rn(o[i][0], o[i][1]);
            p2[1] = __floats2bfloat162_rn(o[i][2], o[i][3]);
        }
    }
}

// ---------------- launch ------------------------------------------------------
extern "C" void kernel_launch(void* const* d_in, const int* in_sizes, int n_in,
                              void* d_out, int out_size) {
    const float* x     = (const float*)d_in[0];
    const float* g1    = (const float*)d_in[2];
    const float* b1    = (const float*)d_in[3];
    const float* wqkv  = (const float*)d_in[4];
    const float* bqkv  = (const float*)d_in[5];
    const float* table = (const float*)d_in[6];
    const float* wproj = (const float*)d_in[7];
    const float* bproj = (const float*)d_in[8];
    const float* g2    = (const float*)d_in[9];
    const float* b2    = (const float*)d_in[10];
    const float* wfc1  = (const float*)d_in[11];
    const float* bfc1  = (const float*)d_in[12];
    const float* wfc2  = (const float*)d_in[13];
    const float* bfc2  = (const float*)d_in[14];
    float* out = (float*)d_out;

    prep_kernel<<<1024, 256>>>(wqkv, wproj, wfc1, wfc2, table);
    ln_kernel<0><<<TOKS / 8, dim3(32, 8)>>>(x, g1, b1);
    gemm_kernel<0><<<dim3(6, TOKS / 128), 256>>>(bqkv, nullptr, nullptr);
    attn_kernel<<<dim3(2048, NHEAD), 128>>>();
    gemm_kernel<1><<<dim3(2, TOKS / 128), 256>>>(bproj, x, nullptr);
    ln_kernel<1><<<TOKS / 8, dim3(32, 8)>>>(nullptr, g2, b2);
    gemm_kernel<2><<<dim3(8, TOKS / 128), 256>>>(bfc1, nullptr, nullptr);
    gemm_kernel<3><<<dim3(2, TOKS / 128), 256>>>(bfc2, nullptr, out);
}

// round 2
// speedup vs baseline: 1.3095x; 1.3095x over previous
#include <cuda_runtime.h>
#include <cuda_bf16.h>
#include <math.h>
#include <stdint.h>

#define TOKS   131072
#define CD     256
#define HIDD   1024
#define NHEAD  8
#define HD     32
#define NWIN   64

typedef __nv_bfloat16 bf16;

// ---------------- scratch ----------------------------------------------------
__device__ bf16  g_xn[(size_t)TOKS * CD];
__device__ bf16  g_qkv[(size_t)TOKS * 3 * CD];
__device__ bf16  g_attn[(size_t)TOKS * CD];
__device__ float g_x1[(size_t)TOKS * CD];
__device__ bf16  g_x1n[(size_t)TOKS * CD];
__device__ bf16  g_h[(size_t)TOKS * HIDD];
__device__ bf16  g_wqkv[768 * 256];
__device__ bf16  g_wproj[256 * 256];
__device__ bf16  g_wfc1[1024 * 256];
__device__ bf16  g_wfc2[256 * 1024];
__device__ float g_bias[NHEAD * NWIN * NWIN];

// ---------------- helpers ----------------------------------------------------
__device__ __forceinline__ void ldsm4(uint32_t* r, uint32_t addr) {
    asm volatile("ldmatrix.sync.aligned.m8n8.x4.shared.b16 {%0,%1,%2,%3}, [%4];\n"
                 : "=r"(r[0]), "=r"(r[1]), "=r"(r[2]), "=r"(r[3]) : "r"(addr));
}
__device__ __forceinline__ void ldsm4t(uint32_t* r, uint32_t addr) {
    asm volatile("ldmatrix.sync.aligned.m8n8.x4.trans.shared.b16 {%0,%1,%2,%3}, [%4];\n"
                 : "=r"(r[0]), "=r"(r[1]), "=r"(r[2]), "=r"(r[3]) : "r"(addr));
}
__device__ __forceinline__ void mma16816(float* c, const uint32_t* a,
                                         uint32_t b0, uint32_t b1) {
    asm volatile("mma.sync.aligned.m16n8k16.row.col.f32.bf16.bf16.f32 "
                 "{%0,%1,%2,%3}, {%4,%5,%6,%7}, {%8,%9}, {%0,%1,%2,%3};\n"
                 : "+f"(c[0]), "+f"(c[1]), "+f"(c[2]), "+f"(c[3])
                 : "r"(a[0]), "r"(a[1]), "r"(a[2]), "r"(a[3]), "r"(b0), "r"(b1));
}
__device__ __forceinline__ void cpasync16(void* dst, const void* src) {
    uint32_t d = (uint32_t)__cvta_generic_to_shared(dst);
    asm volatile("cp.async.cg.shared.global [%0], [%1], 16;\n" :: "r"(d), "l"(src));
}
__device__ __forceinline__ uint32_t smaddr(const void* p) {
    return (uint32_t)__cvta_generic_to_shared(p);
}
__device__ __forceinline__ int token_of(int win, int n) {
    int b  = win >> 6;
    int wr = (win >> 3) & 7;
    int wc = win & 7;
    int r  = n >> 3;
    int c  = n & 7;
    return (b << 12) | (((wr << 3) + r) << 6) | ((wc << 3) + c);
}

// ---------------- prep -------------------------------------------------------
__global__ void prep_kernel(const float* __restrict__ wqkv, const float* __restrict__ wproj,
                            const float* __restrict__ wfc1, const float* __restrict__ wfc2,
                            const float* __restrict__ table) {
    int i = blockIdx.x * 256 + threadIdx.x;
    if (i < 196608) g_wqkv[i] = __float2bfloat16(wqkv[i]);
    if (i < 65536)  g_wproj[i] = __float2bfloat16(wproj[i]);
    if (i < 262144) g_wfc1[i] = __float2bfloat16(wfc1[i]);
    if (i < 262144) g_wfc2[i] = __float2bfloat16(wfc2[i]);
    if (i < 32768) {
        int h = i >> 12;
        int n = (i >> 6) & 63;
        int m = i & 63;
        int rid = ((n >> 3) - (m >> 3) + 7) * 15 + ((n & 7) - (m & 7) + 7);
        g_bias[i] = table[rid * NHEAD + h];
    }
}

// ---------------- LayerNorm --------------------------------------------------
template <int SRC>
__global__ void ln_kernel(const float* __restrict__ x, const float* __restrict__ g,
                          const float* __restrict__ b) {
    int row  = blockIdx.x * 8 + threadIdx.y;
    int lane = threadIdx.x;
    const float* xr = (SRC == 0 ? x : g_x1) + (size_t)row * CD;
    float v[8];
    float s = 0.f;
#pragma unroll
    for (int i = 0; i < 8; i++) { v[i] = xr[lane + 32 * i]; s += v[i]; }
#pragma unroll
    for (int o = 16; o; o >>= 1) s += __shfl_xor_sync(0xffffffffu, s, o);
    float mu = s * (1.f / 256.f);
    float q = 0.f;
#pragma unroll
    for (int i = 0; i < 8; i++) { float d = v[i] - mu; q += d * d; }
#pragma unroll
    for (int o = 16; o; o >>= 1) q += __shfl_xor_sync(0xffffffffu, q, o);
    float inv = rsqrtf(q * (1.f / 256.f) + 1e-5f);
    bf16* orow = (SRC == 0 ? g_xn : g_x1n) + (size_t)row * CD;
#pragma unroll
    for (int i = 0; i < 8; i++) {
        int c = lane + 32 * i;
        orow[c] = __float2bfloat16((v[i] - mu) * inv * g[c] + b[c]);
    }
}

// ---------------- GEMM (double-buffered cp.async) ----------------------------
// C[M,N] = A[M,K] @ W[N,K]^T (+epilogue). BM=128 BN=128 BK=64, 256 threads.
template <int MODE>
__global__ void __launch_bounds__(256, 2) gemm_kernel(const float* __restrict__ bias,
                                                      const float* __restrict__ res,
                                                      float* __restrict__ outf) {
    constexpr int KD = (MODE == 3) ? 1024 : 256;
    constexpr int ND = (MODE == 0) ? 768 : (MODE == 2) ? 1024 : 256;
    const bf16* A = (MODE == 0) ? g_xn : (MODE == 1) ? g_attn : (MODE == 2) ? g_x1n : g_h;
    const bf16* W = (MODE == 0) ? g_wqkv : (MODE == 1) ? g_wproj : (MODE == 2) ? g_wfc1 : g_wfc2;

    extern __shared__ __align__(16) bf16 smem[];   // As[2][128][72] | Bs[2][128][72]

    int tid  = threadIdx.x;
    int lane = tid & 31;
    int wid  = tid >> 5;
    int wm   = wid & 3;
    int wn   = wid >> 2;
    int m0   = blockIdx.y * 128;
    int n0   = blockIdx.x * 128;

    float acc[2][8][4];
#pragma unroll
    for (int i = 0; i < 2; i++)
#pragma unroll
        for (int j = 0; j < 8; j++)
#pragma unroll
            for (int k = 0; k < 4; k++) acc[i][j][k] = 0.f;

    int lr = tid >> 3;
    int lc = (tid & 7) << 3;

    auto load_tile = [&](int buf, int kt) {
        const bf16* Ag = A + (size_t)(m0 + lr) * KD + kt + lc;
        const bf16* Wg = W + (size_t)(n0 + lr) * KD + kt + lc;
        bf16* As = smem + buf * 9216;
        bf16* Bs = smem + 18432 + buf * 9216;
#pragma unroll
        for (int p = 0; p < 4; p++) {
            cpasync16(&As[(lr + 32 * p) * 72 + lc], Ag + (size_t)32 * p * KD);
            cpasync16(&Bs[(lr + 32 * p) * 72 + lc], Wg + (size_t)32 * p * KD);
        }
    };

    load_tile(0, 0);
    asm volatile("cp.async.commit_group;\n");

    constexpr int NK = KD / 64;
    for (int i = 0; i < NK; i++) {
        if (i + 1 < NK) {
            load_tile((i + 1) & 1, (i + 1) * 64);
            asm volatile("cp.async.commit_group;\n");
            asm volatile("cp.async.wait_group 1;\n");
        } else {
            asm volatile("cp.async.wait_group 0;\n");
        }
        __syncthreads();
        const bf16* As = smem + (i & 1) * 9216;
        const bf16* Bs = smem + 18432 + (i & 1) * 9216;
#pragma unroll
        for (int ks = 0; ks < 4; ks++) {
            uint32_t a[2][4], b[4][4];
#pragma unroll
            for (int mf = 0; mf < 2; mf++)
                ldsm4(a[mf], smaddr(&As[(wm * 32 + mf * 16 + (lane & 15)) * 72 +
                                        ks * 16 + ((lane >> 4) << 3)]));
#pragma unroll
            for (int np = 0; np < 4; np++)
                ldsm4(b[np], smaddr(&Bs[(wn * 64 + np * 16 + ((lane >> 4) << 3) + (lane & 7)) * 72 +
                                        ks * 16 + (((lane >> 3) & 1) << 3)]));
#pragma unroll
            for (int mf = 0; mf < 2; mf++)
#pragma unroll
                for (int nf = 0; nf < 8; nf++)
                    mma16816(acc[mf][nf], a[mf], b[nf >> 1][(nf & 1) * 2],
                             b[nf >> 1][(nf & 1) * 2 + 1]);
        }
        __syncthreads();
    }

    int er = lane >> 2;
    int ec = (lane & 3) << 1;
#pragma unroll
    for (int mf = 0; mf < 2; mf++) {
#pragma unroll
        for (int nf = 0; nf < 8; nf++) {
            int col = n0 + wn * 64 + nf * 8 + ec;
            float bx = bias[col], by = bias[col + 1];
#pragma unroll
            for (int half = 0; half < 2; half++) {
                int row = m0 + wm * 32 + mf * 16 + er + half * 8;
                float v0 = acc[mf][nf][half * 2] + bx;
                float v1 = acc[mf][nf][half * 2 + 1] + by;
                size_t o = (size_t)row * ND + col;
                if (MODE == 0) {
                    *(__nv_bfloat162*)(g_qkv + o) = __floats2bfloat162_rn(v0, v1);
                } else if (MODE == 1) {
                    float2 r2 = *(const float2*)&res[o];
                    g_x1[o]     = v0 + r2.x;
                    g_x1[o + 1] = v1 + r2.y;
                } else if (MODE == 2) {
                    float gx = 0.5f * v0 * (1.0f + erff(v0 * 0.70710678118654752f));
                    float gy = 0.5f * v1 * (1.0f + erff(v1 * 0.70710678118654752f));
                    *(__nv_bfloat162*)(g_h + o) = __floats2bfloat162_rn(gx, gy);
                } else {
                    float2 r2 = *(const float2*)&g_x1[o];
                    outf[o]     = v0 + r2.x;
                    outf[o + 1] = v1 + r2.y;
                }
            }
        }
    }
}

// ---------------- Attention: tensor cores, one block per window --------------
// 512 threads = 16 warps; warp (h, half): head h, S-rows [half*32, half*32+32).
// SMEM: Q/K/V staged as [head][64][40] bf16 (stride 40 -> conflict-free ldmatrix).
__global__ void __launch_bounds__(512, 1) attn_kernel() {
    extern __shared__ __align__(16) bf16 sm[];
    bf16* Qs = sm;
    bf16* Ks = sm + 20480;
    bf16* Vs = sm + 40960;

    int win  = blockIdx.x;
    int tid  = threadIdx.x;
    int lane = tid & 31;
    int wid  = tid >> 5;

    // stage QKV for this window
    for (int u = tid; u < 6144; u += 512) {
        int tok = u / 96;
        int r   = u - tok * 96;
        int sec = r >> 5;
        int w   = r & 31;
        int h   = w >> 2;
        int dp  = (w & 3) << 3;
        uint4 val = *(const uint4*)(g_qkv + (size_t)token_of(win, tok) * 768 +
                                    sec * 256 + h * 32 + dp);
        *(uint4*)(sm + sec * 20480 + (h * 64 + tok) * 40 + dp) = val;
    }
    __syncthreads();

    int h  = wid >> 1;
    int m0 = (wid & 1) << 5;
    const bf16* Qh = Qs + h * 2560;
    const bf16* Kh = Ks + h * 2560;
    const bf16* Vh = Vs + h * 2560;

    // S = Q K^T   (32 rows x 64 cols per warp)
    float s[2][8][4];
#pragma unroll
    for (int i = 0; i < 2; i++)
#pragma unroll
        for (int j = 0; j < 8; j++)
#pragma unroll
            for (int k = 0; k < 4; k++) s[i][j][k] = 0.f;

#pragma unroll
    for (int ks = 0; ks < 2; ks++) {
        uint32_t a[2][4];
#pragma unroll
        for (int mt = 0; mt < 2; mt++)
            ldsm4(a[mt], smaddr(&Qh[(m0 + mt * 16 + (lane & 15)) * 40 +
                                    ks * 16 + ((lane >> 4) << 3)]));
#pragma unroll
        for (int np = 0; np < 4; np++) {
            uint32_t b[4];
            ldsm4(b, smaddr(&Kh[(np * 16 + ((lane >> 4) << 3) + (lane & 7)) * 40 +
                                ks * 16 + (((lane >> 3) & 1) << 3)]));
#pragma unroll
            for (int mt = 0; mt < 2; mt++) {
                mma16816(s[mt][np * 2],     a[mt], b[0], b[1]);
                mma16816(s[mt][np * 2 + 1], a[mt], b[2], b[3]);
            }
        }
    }

    // softmax (rows owned by quads), scale + bias folded here
    int q  = lane >> 2;
    int c2 = (lane & 3) << 1;
    const float* bh = g_bias + (h << 12);
    const float scale = 0.17677669529663687f;
    uint32_t p[2][8][2];
#pragma unroll
    for (int mt = 0; mt < 2; mt++) {
#pragma unroll
        for (int hr = 0; hr < 2; hr++) {
            int gr = m0 + mt * 16 + hr * 8 + q;
            float v[16];
            float mx = -1e30f;
#pragma unroll
            for (int nt = 0; nt < 8; nt++) {
                float2 bb = *(const float2*)(bh + (gr << 6) + nt * 8 + c2);
                float v0 = fmaf(s[mt][nt][hr * 2],     scale, bb.x);
                float v1 = fmaf(s[mt][nt][hr * 2 + 1], scale, bb.y);
                v[nt * 2] = v0; v[nt * 2 + 1] = v1;
                mx = fmaxf(mx, fmaxf(v0, v1));
            }
            mx = fmaxf(mx, __shfl_xor_sync(0xffffffffu, mx, 1));
            mx = fmaxf(mx, __shfl_xor_sync(0xffffffffu, mx, 2));
            float sum = 0.f;
#pragma unroll
            for (int e = 0; e < 16; e++) { v[e] = __expf(v[e] - mx); sum += v[e]; }
            sum += __shfl_xor_sync(0xffffffffu, sum, 1);
            sum += __shfl_xor_sync(0xffffffffu, sum, 2);
            float inv = 1.f / sum;
#pragma unroll
            for (int nt = 0; nt < 8; nt++) {
                __nv_bfloat162 pk = __floats2bfloat162_rn(v[nt * 2] * inv, v[nt * 2 + 1] * inv);
                p[mt][nt][hr] = *(uint32_t*)&pk;
            }
        }
    }

    // O = P V   (32 rows x 32 dims per warp)
    float o[2][4][4];
#pragma unroll
    for (int i = 0; i < 2; i++)
#pragma unroll
        for (int j = 0; j < 4; j++)
#pragma unroll
            for (int k = 0; k < 4; k++) o[i][j][k] = 0.f;

#pragma unroll
    for (int kt = 0; kt < 4; kt++) {
        uint32_t a0[4] = {p[0][2 * kt][0], p[0][2 * kt][1], p[0][2 * kt + 1][0], p[0][2 * kt + 1][1]};
        uint32_t a1[4] = {p[1][2 * kt][0], p[1][2 * kt][1], p[1][2 * kt + 1][0], p[1][2 * kt + 1][1]};
#pragma unroll
        for (int np = 0; np < 2; np++) {
            uint32_t b[4];
            ldsm4t(b, smaddr(&Vh[(kt * 16 + ((lane >> 3) & 1) * 8 + (lane & 7)) * 40 +
                                 np * 16 + ((lane >> 4) << 3)]));
            mma16816(o[0][np * 2],     a0, b[0], b[1]);
            mma16816(o[0][np * 2 + 1], a0, b[2], b[3]);
            mma16816(o[1][np * 2],     a1, b[0], b[1]);
            mma16816(o[1][np * 2 + 1], a1, b[2], b[3]);
        }
    }

#pragma unroll
    for (int mt = 0; mt < 2; mt++)
#pragma unroll
        for (int hr = 0; hr < 2; hr++) {
            int gr = m0 + mt * 16 + hr * 8 + q;
            size_t base = (size_t)token_of(win, gr) * 256 + h * 32;
#pragma unroll
            for (int nt = 0; nt < 4; nt++) {
                *(__nv_bfloat162*)(g_attn + base + nt * 8 + c2) =
                    __floats2bfloat162_rn(o[mt][nt][hr * 2], o[mt][nt][hr * 2 + 1]);
            }
        }
}

// ---------------- launch ------------------------------------------------------
extern "C" void kernel_launch(void* const* d_in, const int* in_sizes, int n_in,
                              void* d_out, int out_size) {
    const float* x     = (const float*)d_in[0];
    const float* g1    = (const float*)d_in[2];
    const float* b1    = (const float*)d_in[3];
    const float* wqkv  = (const float*)d_in[4];
    const float* bqkv  = (const float*)d_in[5];
    const float* table = (const float*)d_in[6];
    const float* wproj = (const float*)d_in[7];
    const float* bproj = (const float*)d_in[8];
    const float* g2    = (const float*)d_in[9];
    const float* b2    = (const float*)d_in[10];
    const float* wfc1  = (const float*)d_in[11];
    const float* bfc1  = (const float*)d_in[12];
    const float* wfc2  = (const float*)d_in[13];
    const float* bfc2  = (const float*)d_in[14];
    float* out = (float*)d_out;

    cudaFuncSetAttribute(attn_kernel, cudaFuncAttributeMaxDynamicSharedMemorySize, 122880);
    cudaFuncSetAttribute(gemm_kernel<0>, cudaFuncAttributeMaxDynamicSharedMemorySize, 73728);
    cudaFuncSetAttribute(gemm_kernel<1>, cudaFuncAttributeMaxDynamicSharedMemorySize, 73728);
    cudaFuncSetAttribute(gemm_kernel<2>, cudaFuncAttributeMaxDynamicSharedMemorySize, 73728);
    cudaFuncSetAttribute(gemm_kernel<3>, cudaFuncAttributeMaxDynamicSharedMemorySize, 73728);

    prep_kernel<<<1024, 256>>>(wqkv, wproj, wfc1, wfc2, table);
    ln_kernel<0><<<TOKS / 8, dim3(32, 8)>>>(x, g1, b1);
    gemm_kernel<0><<<dim3(6, TOKS / 128), 256, 73728>>>(bqkv, nullptr, nullptr);
    attn_kernel<<<2048, 512, 122880>>>();
    gemm_kernel<1><<<dim3(2, TOKS / 128), 256, 73728>>>(bproj, x, nullptr);
    ln_kernel<1><<<TOKS / 8, dim3(32, 8)>>>(nullptr, g2, b2);
    gemm_kernel<2><<<dim3(8, TOKS / 128), 256, 73728>>>(bfc1, nullptr, nullptr);
    gemm_kernel<3><<<dim3(2, TOKS / 128), 256, 73728>>>(bfc2, nullptr, out);
}

// round 3
// speedup vs baseline: 1.3864x; 1.0588x over previous
#include <cuda_runtime.h>
#include <cuda_bf16.h>
#include <math.h>
#include <stdint.h>

#define TOKS   131072
#define CD     256
#define HIDD   1024
#define NHEAD  8
#define HD     32
#define NWIN   64

typedef __nv_bfloat16 bf16;

// ---------------- scratch ----------------------------------------------------
// g_xn, g_qkv, g_attn are WINDOW-MAJOR: row index = win*64 + n.
__device__ bf16  g_xn[(size_t)TOKS * CD];
__device__ bf16  g_qkv[(size_t)TOKS * 3 * CD];
__device__ bf16  g_attn[(size_t)TOKS * CD];
__device__ float g_x1[(size_t)TOKS * CD];          // token-major
__device__ bf16  g_x1n[(size_t)TOKS * CD];         // token-major
__device__ bf16  g_h[(size_t)TOKS * HIDD];         // token-major
__device__ bf16  g_wqkv[768 * 256];
__device__ bf16  g_wproj[256 * 256];
__device__ bf16  g_wfc1[1024 * 256];
__device__ bf16  g_wfc2[256 * 1024];
__device__ float g_bias[NHEAD * NWIN * NWIN];

// ---------------- helpers ----------------------------------------------------
__device__ __forceinline__ void ldsm4(uint32_t* r, uint32_t addr) {
    asm volatile("ldmatrix.sync.aligned.m8n8.x4.shared.b16 {%0,%1,%2,%3}, [%4];\n"
                 : "=r"(r[0]), "=r"(r[1]), "=r"(r[2]), "=r"(r[3]) : "r"(addr));
}
__device__ __forceinline__ void ldsm4t(uint32_t* r, uint32_t addr) {
    asm volatile("ldmatrix.sync.aligned.m8n8.x4.trans.shared.b16 {%0,%1,%2,%3}, [%4];\n"
                 : "=r"(r[0]), "=r"(r[1]), "=r"(r[2]), "=r"(r[3]) : "r"(addr));
}
__device__ __forceinline__ void mma16816(float* c, const uint32_t* a,
                                         uint32_t b0, uint32_t b1) {
    asm volatile("mma.sync.aligned.m16n8k16.row.col.f32.bf16.bf16.f32 "
                 "{%0,%1,%2,%3}, {%4,%5,%6,%7}, {%8,%9}, {%0,%1,%2,%3};\n"
                 : "+f"(c[0]), "+f"(c[1]), "+f"(c[2]), "+f"(c[3])
                 : "r"(a[0]), "r"(a[1]), "r"(a[2]), "r"(a[3]), "r"(b0), "r"(b1));
}
__device__ __forceinline__ void cpasync16(void* dst, const void* src) {
    uint32_t d = (uint32_t)__cvta_generic_to_shared(dst);
    asm volatile("cp.async.cg.shared.global [%0], [%1], 16;\n" :: "r"(d), "l"(src));
}
__device__ __forceinline__ uint32_t smaddr(const void* p) {
    return (uint32_t)__cvta_generic_to_shared(p);
}
// window-order row -> token index
__device__ __forceinline__ int token_of(int win, int n) {
    int b  = win >> 6;
    int wr = (win >> 3) & 7;
    int wc = win & 7;
    int r  = n >> 3;
    int c  = n & 7;
    return (b << 12) | (((wr << 3) + r) << 6) | ((wc << 3) + c);
}

// ---------------- prep -------------------------------------------------------
__global__ void prep_kernel(const float* __restrict__ wqkv, const float* __restrict__ wproj,
                            const float* __restrict__ wfc1, const float* __restrict__ wfc2,
                            const float* __restrict__ table) {
    int i = blockIdx.x * 256 + threadIdx.x;
    if (i < 196608) g_wqkv[i] = __float2bfloat16(wqkv[i]);
    if (i < 65536)  g_wproj[i] = __float2bfloat16(wproj[i]);
    if (i < 262144) g_wfc1[i] = __float2bfloat16(wfc1[i]);
    if (i < 262144) g_wfc2[i] = __float2bfloat16(wfc2[i]);
    if (i < 32768) {
        int h = i >> 12;
        int n = (i >> 6) & 63;
        int m = i & 63;
        int rid = ((n >> 3) - (m >> 3) + 7) * 15 + ((n & 7) - (m & 7) + 7);
        g_bias[i] = table[rid * NHEAD + h];
    }
}

// ---------------- LayerNorm --------------------------------------------------
// SRC==0: read x (token-major), write g_xn WINDOW-MAJOR (bf16).
// SRC==1: read g_x1 (token-major), write g_x1n token-major (bf16).
template <int SRC>
__global__ void ln_kernel(const float* __restrict__ x, const float* __restrict__ g,
                          const float* __restrict__ b) {
    int row  = blockIdx.x * 8 + threadIdx.y;   // token index
    int lane = threadIdx.x;
    const float* xr = (SRC == 0 ? x : g_x1) + (size_t)row * CD;
    float v[8];
    float s = 0.f;
#pragma unroll
    for (int i = 0; i < 8; i++) { v[i] = xr[lane + 32 * i]; s += v[i]; }
#pragma unroll
    for (int o = 16; o; o >>= 1) s += __shfl_xor_sync(0xffffffffu, s, o);
    float mu = s * (1.f / 256.f);
    float q = 0.f;
#pragma unroll
    for (int i = 0; i < 8; i++) { float d = v[i] - mu; q += d * d; }
#pragma unroll
    for (int o = 16; o; o >>= 1) q += __shfl_xor_sync(0xffffffffu, q, o);
    float inv = rsqrtf(q * (1.f / 256.f) + 1e-5f);

    int orow;
    if (SRC == 0) {
        int bb  = row >> 12;
        int rem = row & 4095;
        int hr  = rem >> 6;
        int c   = rem & 63;
        int win = (bb << 6) | ((hr >> 3) << 3) | (c >> 3);
        int n   = ((hr & 7) << 3) | (c & 7);
        orow = (win << 6) | n;
    } else {
        orow = row;
    }
    bf16* po = (SRC == 0 ? g_xn : g_x1n) + (size_t)orow * CD;
#pragma unroll
    for (int i = 0; i < 8; i++) {
        int c = lane + 32 * i;
        po[c] = __float2bfloat16((v[i] - mu) * inv * g[c] + b[c]);
    }
}

// ---------------- GEMM (double-buffered cp.async) ----------------------------
// C[M,N] = A[M,K] @ W[N,K]^T (+epilogue). BM=128 BN=128 BK=64, 256 threads.
// MODE 0: qkv  (window-major in/out)          MODE 1: proj (win-major A, scatter rows)
// MODE 2: fc1 (+gelu)                         MODE 3: fc2 (+residual -> out)
template <int MODE>
__global__ void __launch_bounds__(256, 2) gemm_kernel(const float* __restrict__ bias,
                                                      const float* __restrict__ res,
                                                      float* __restrict__ outf) {
    constexpr int KD = (MODE == 3) ? 1024 : 256;
    constexpr int ND = (MODE == 0) ? 768 : (MODE == 2) ? 1024 : 256;
    const bf16* A = (MODE == 0) ? g_xn : (MODE == 1) ? g_attn : (MODE == 2) ? g_x1n : g_h;
    const bf16* W = (MODE == 0) ? g_wqkv : (MODE == 1) ? g_wproj : (MODE == 2) ? g_wfc1 : g_wfc2;

    extern __shared__ __align__(16) bf16 smem[];   // As[2][128][72] | Bs[2][128][72]

    int tid  = threadIdx.x;
    int lane = tid & 31;
    int wid  = tid >> 5;
    int wm   = wid & 3;
    int wn   = wid >> 2;
    int m0   = blockIdx.y * 128;
    int n0   = blockIdx.x * 128;

    float acc[2][8][4];
#pragma unroll
    for (int i = 0; i < 2; i++)
#pragma unroll
        for (int j = 0; j < 8; j++)
#pragma unroll
            for (int k = 0; k < 4; k++) acc[i][j][k] = 0.f;

    int lr = tid >> 3;
    int lc = (tid & 7) << 3;

    auto load_tile = [&](int buf, int kt) {
        const bf16* Ag = A + (size_t)(m0 + lr) * KD + kt + lc;
        const bf16* Wg = W + (size_t)(n0 + lr) * KD + kt + lc;
        bf16* As = smem + buf * 9216;
        bf16* Bs = smem + 18432 + buf * 9216;
#pragma unroll
        for (int p = 0; p < 4; p++) {
            cpasync16(&As[(lr + 32 * p) * 72 + lc], Ag + (size_t)32 * p * KD);
            cpasync16(&Bs[(lr + 32 * p) * 72 + lc], Wg + (size_t)32 * p * KD);
        }
    };

    load_tile(0, 0);
    asm volatile("cp.async.commit_group;\n");

    constexpr int NK = KD / 64;
#pragma unroll
    for (int i = 0; i < NK; i++) {
        if (i + 1 < NK) {
            load_tile((i + 1) & 1, (i + 1) * 64);
            asm volatile("cp.async.commit_group;\n");
            asm volatile("cp.async.wait_group 1;\n");
        } else {
            asm volatile("cp.async.wait_group 0;\n");
        }
        __syncthreads();
        const bf16* As = smem + (i & 1) * 9216;
        const bf16* Bs = smem + 18432 + (i & 1) * 9216;
#pragma unroll
        for (int ks = 0; ks < 4; ks++) {
            uint32_t a[2][4], b[4][4];
#pragma unroll
            for (int mf = 0; mf < 2; mf++)
                ldsm4(a[mf], smaddr(&As[(wm * 32 + mf * 16 + (lane & 15)) * 72 +
                                        ks * 16 + ((lane >> 4) << 3)]));
#pragma unroll
            for (int np = 0; np < 4; np++)
                ldsm4(b[np], smaddr(&Bs[(wn * 64 + np * 16 + ((lane >> 4) << 3) + (lane & 7)) * 72 +
                                        ks * 16 + (((lane >> 3) & 1) << 3)]));
#pragma unroll
            for (int mf = 0; mf < 2; mf++)
#pragma unroll
                for (int nf = 0; nf < 8; nf++)
                    mma16816(acc[mf][nf], a[mf], b[nf >> 1][(nf & 1) * 2],
                             b[nf >> 1][(nf & 1) * 2 + 1]);
        }
        __syncthreads();
    }

    int er = lane >> 2;
    int ec = (lane & 3) << 1;
#pragma unroll
    for (int mf = 0; mf < 2; mf++) {
#pragma unroll
        for (int nf = 0; nf < 8; nf++) {
            int col = n0 + wn * 64 + nf * 8 + ec;
            float bx = bias[col], by = bias[col + 1];
#pragma unroll
            for (int half = 0; half < 2; half++) {
                int row = m0 + wm * 32 + mf * 16 + er + half * 8;
                float v0 = acc[mf][nf][half * 2] + bx;
                float v1 = acc[mf][nf][half * 2 + 1] + by;
                if (MODE == 0) {
                    size_t o = (size_t)row * ND + col;
                    *(__nv_bfloat162*)(g_qkv + o) = __floats2bfloat162_rn(v0, v1);
                } else if (MODE == 1) {
                    int trow = token_of(row >> 6, row & 63);
                    size_t o = (size_t)trow * ND + col;
                    float2 r2 = *(const float2*)&res[o];
                    g_x1[o]     = v0 + r2.x;
                    g_x1[o + 1] = v1 + r2.y;
                } else if (MODE == 2) {
                    size_t o = (size_t)row * ND + col;
                    float gx = 0.5f * v0 * (1.0f + erff(v0 * 0.70710678118654752f));
                    float gy = 0.5f * v1 * (1.0f + erff(v1 * 0.70710678118654752f));
                    *(__nv_bfloat162*)(g_h + o) = __floats2bfloat162_rn(gx, gy);
                } else {
                    size_t o = (size_t)row * ND + col;
                    float2 r2 = *(const float2*)&g_x1[o];
                    outf[o]     = v0 + r2.x;
                    outf[o + 1] = v1 + r2.y;
                }
            }
        }
    }
}

// ---------------- Attention: one block = (window, 4 heads) -------------------
// 256 threads = 8 warps; warp (h', half): local head h', S-rows [half*32,+32).
// SMEM: Q/K/V [4][64][40] bf16 each (61440 B total) -> 3 CTAs/SM.
__global__ void __launch_bounds__(256, 3) attn_kernel() {
    extern __shared__ __align__(16) bf16 sm[];
    bf16* Qs = sm;
    bf16* Ks = sm + 10240;
    bf16* Vs = sm + 20480;

    int win  = blockIdx.x;
    int hh   = blockIdx.y;          // head half: 0 -> heads 0-3, 1 -> heads 4-7
    int tid  = threadIdx.x;
    int lane = tid & 31;
    int wid  = tid >> 5;

    // stage QKV (fully coalesced: g_qkv is window-major)
    for (int u = tid; u < 3072; u += 256) {
        int tok = u / 48;
        int r   = u - tok * 48;
        int sec = r >> 4;
        int w   = r & 15;
        int h   = w >> 2;
        int dp  = (w & 3) << 3;
        uint4 val = *(const uint4*)(g_qkv + (size_t)((win << 6) + tok) * 768 +
                                    sec * 256 + ((hh << 2) + h) * 32 + dp);
        *(uint4*)(sm + sec * 10240 + (h * 64 + tok) * 40 + dp) = val;
    }
    __syncthreads();

    int h  = wid >> 1;              // local head 0..3
    int gh = (hh << 2) + h;         // global head
    int m0 = (wid & 1) << 5;
    const bf16* Qh = Qs + h * 2560;
    const bf16* Kh = Ks + h * 2560;
    const bf16* Vh = Vs + h * 2560;

    // S = Q K^T
    float s[2][8][4];
#pragma unroll
    for (int i = 0; i < 2; i++)
#pragma unroll
        for (int j = 0; j < 8; j++)
#pragma unroll
            for (int k = 0; k < 4; k++) s[i][j][k] = 0.f;

#pragma unroll
    for (int ks = 0; ks < 2; ks++) {
        uint32_t a[2][4];
#pragma unroll
        for (int mt = 0; mt < 2; mt++)
            ldsm4(a[mt], smaddr(&Qh[(m0 + mt * 16 + (lane & 15)) * 40 +
                                    ks * 16 + ((lane >> 4) << 3)]));
#pragma unroll
        for (int np = 0; np < 4; np++) {
            uint32_t b[4];
            ldsm4(b, smaddr(&Kh[(np * 16 + ((lane >> 4) << 3) + (lane & 7)) * 40 +
                                ks * 16 + (((lane >> 3) & 1) << 3)]));
#pragma unroll
            for (int mt = 0; mt < 2; mt++) {
                mma16816(s[mt][np * 2],     a[mt], b[0], b[1]);
                mma16816(s[mt][np * 2 + 1], a[mt], b[2], b[3]);
            }
        }
    }

    // softmax (quad-owned rows), scale + bias folded
    int q  = lane >> 2;
    int c2 = (lane & 3) << 1;
    const float* bh = g_bias + (gh << 12);
    const float scale = 0.17677669529663687f;
    uint32_t p[2][8][2];
#pragma unroll
    for (int mt = 0; mt < 2; mt++) {
#pragma unroll
        for (int hr = 0; hr < 2; hr++) {
            int gr = m0 + mt * 16 + hr * 8 + q;
            float v[16];
            float mx = -1e30f;
#pragma unroll
            for (int nt = 0; nt < 8; nt++) {
                float2 bb = *(const float2*)(bh + (gr << 6) + nt * 8 + c2);
                float v0 = fmaf(s[mt][nt][hr * 2],     scale, bb.x);
                float v1 = fmaf(s[mt][nt][hr * 2 + 1], scale, bb.y);
                v[nt * 2] = v0; v[nt * 2 + 1] = v1;
                mx = fmaxf(mx, fmaxf(v0, v1));
            }
            mx = fmaxf(mx, __shfl_xor_sync(0xffffffffu, mx, 1));
            mx = fmaxf(mx, __shfl_xor_sync(0xffffffffu, mx, 2));
            float sum = 0.f;
#pragma unroll
            for (int e = 0; e < 16; e++) { v[e] = __expf(v[e] - mx); sum += v[e]; }
            sum += __shfl_xor_sync(0xffffffffu, sum, 1);
            sum += __shfl_xor_sync(0xffffffffu, sum, 2);
            float inv = 1.f / sum;
#pragma unroll
            for (int nt = 0; nt < 8; nt++) {
                __nv_bfloat162 pk = __floats2bfloat162_rn(v[nt * 2] * inv, v[nt * 2 + 1] * inv);
                p[mt][nt][hr] = *(uint32_t*)&pk;
            }
        }
    }

    // O = P V
    float o[2][4][4];
#pragma unroll
    for (int i = 0; i < 2; i++)
#pragma unroll
        for (int j = 0; j < 4; j++)
#pragma unroll
            for (int k = 0; k < 4; k++) o[i][j][k] = 0.f;

#pragma unroll
    for (int kt = 0; kt < 4; kt++) {
        uint32_t a0[4] = {p[0][2 * kt][0], p[0][2 * kt][1], p[0][2 * kt + 1][0], p[0][2 * kt + 1][1]};
        uint32_t a1[4] = {p[1][2 * kt][0], p[1][2 * kt][1], p[1][2 * kt + 1][0], p[1][2 * kt + 1][1]};
#pragma unroll
        for (int np = 0; np < 2; np++) {
            uint32_t b[4];
            ldsm4t(b, smaddr(&Vh[(kt * 16 + ((lane >> 3) & 1) * 8 + (lane & 7)) * 40 +
                                 np * 16 + ((lane >> 4) << 3)]));
            mma16816(o[0][np * 2],     a0, b[0], b[1]);
            mma16816(o[0][np * 2 + 1], a0, b[2], b[3]);
            mma16816(o[1][np * 2],     a1, b[0], b[1]);
            mma16816(o[1][np * 2 + 1], a1, b[2], b[3]);
        }
    }

#pragma unroll
    for (int mt = 0; mt < 2; mt++)
#pragma unroll
        for (int hr = 0; hr < 2; hr++) {
            int gr = m0 + mt * 16 + hr * 8 + q;
            size_t base = (size_t)((win << 6) + gr) * 256 + gh * 32;   // window-major
#pragma unroll
            for (int nt = 0; nt < 4; nt++) {
                *(__nv_bfloat162*)(g_attn + base + nt * 8 + c2) =
                    __floats2bfloat162_rn(o[mt][nt][hr * 2], o[mt][nt][hr * 2 + 1]);
            }
        }
}

// ---------------- launch ------------------------------------------------------
extern "C" void kernel_launch(void* const* d_in, const int* in_sizes, int n_in,
                              void* d_out, int out_size) {
    const float* x     = (const float*)d_in[0];
    const float* g1    = (const float*)d_in[2];
    const float* b1    = (const float*)d_in[3];
    const float* wqkv  = (const float*)d_in[4];
    const float* bqkv  = (const float*)d_in[5];
    const float* table = (const float*)d_in[6];
    const float* wproj = (const float*)d_in[7];
    const float* bproj = (const float*)d_in[8];
    const float* g2    = (const float*)d_in[9];
    const float* b2    = (const float*)d_in[10];
    const float* wfc1  = (const float*)d_in[11];
    const float* bfc1  = (const float*)d_in[12];
    const float* wfc2  = (const float*)d_in[13];
    const float* bfc2  = (const float*)d_in[14];
    float* out = (float*)d_out;

    cudaFuncSetAttribute(attn_kernel, cudaFuncAttributeMaxDynamicSharedMemorySize, 61440);
    cudaFuncSetAttribute(gemm_kernel<0>, cudaFuncAttributeMaxDynamicSharedMemorySize, 73728);
    cudaFuncSetAttribute(gemm_kernel<1>, cudaFuncAttributeMaxDynamicSharedMemorySize, 73728);
    cudaFuncSetAttribute(gemm_kernel<2>, cudaFuncAttributeMaxDynamicSharedMemorySize, 73728);
    cudaFuncSetAttribute(gemm_kernel<3>, cudaFuncAttributeMaxDynamicSharedMemorySize, 73728);

    prep_kernel<<<1024, 256>>>(wqkv, wproj, wfc1, wfc2, table);
    ln_kernel<0><<<TOKS / 8, dim3(32, 8)>>>(x, g1, b1);
    gemm_kernel<0><<<dim3(6, TOKS / 128), 256, 73728>>>(bqkv, nullptr, nullptr);
    attn_kernel<<<dim3(2048, 2), 256, 61440>>>();
    gemm_kernel<1><<<dim3(2, TOKS / 128), 256, 73728>>>(bproj, x, nullptr);
    ln_kernel<1><<<TOKS / 8, dim3(32, 8)>>>(nullptr, g2, b2);
    gemm_kernel<2><<<dim3(8, TOKS / 128), 256, 73728>>>(bfc1, nullptr, nullptr);
    gemm_kernel<3><<<dim3(2, TOKS / 128), 256, 73728>>>(bfc2, nullptr, out);
}